// round 8
// baseline (speedup 1.0000x reference)
#include <cuda_runtime.h>
#include <cuda_bf16.h>

#define BB    16
#define MM    256
#define NN    8192
#define NFG   128
#define NBG   384
#define SAMP  512
#define NBINS 256
#define LISTCAP 2048
#define NCTA  128
#define NTHR  256

__device__ unsigned g_keyFg[BB * NN];          // f2s(pri) if fg else 0
__device__ unsigned g_keyBg[BB * NN];          // f2s(pri) if bg else 0
__device__ unsigned g_hist[2 * BB * NBINS];    // [side][b][bin]; zeroed in phase3
__device__ unsigned g_arrive;                  // monotone grid-barrier counter

static __device__ __forceinline__ unsigned f2s(float f) {
    unsigned u = __float_as_uint(f);
    return (u & 0x80000000u) ? ~u : (u | 0x80000000u);
}

__global__ __launch_bounds__(NTHR, 1)
void fused_kernel(const float4* __restrict__ gt,
                  const float4* __restrict__ prop,
                  const float*  __restrict__ pri,
                  const int*    __restrict__ gtc,
                  float* __restrict__ mv,
                  float* __restrict__ mi,
                  float* __restrict__ s_idx,
                  float* __restrict__ s_cls,
                  float* __restrict__ s_gt) {
    __shared__ float4 g[MM];
    __shared__ float  ga[MM];
    __shared__ unsigned long long list[LISTCAP];
    __shared__ unsigned warpsum[8];
    __shared__ int listCnt, sh_T, sh_total;

    const int tid = threadIdx.x;                 // 256
    const int c   = blockIdx.x;                  // 128
    const int lane = tid & 31;
    const int wid  = tid >> 5;

    // ===================== Phase 1: match (8 CTAs per batch) ================
    {
        const int b = c >> 3;                    // batch
        const int q = c & 7;                     // 1024-proposal slice
        {
            float4 v = gt[b * MM + tid];
            g[tid] = v;
            ga[tid] = __fmul_rn(v.z - v.x, v.w - v.y);
        }
        __syncthreads();

        int   n[4];
        float4 p[4];
        float ap[4], pr[4];
        float bI[4], bU[4];
        int   bx[4];
#pragma unroll
        for (int j = 0; j < 4; ++j) {
            n[j] = b * NN + q * 1024 + j * 256 + tid;
            p[j] = prop[n[j]];
            pr[j] = pri[n[j]];
            ap[j] = __fmul_rn(p[j].z - p[j].x, p[j].w - p[j].y);
            bI[j] = -1.0f; bU[j] = 1.0f; bx[j] = 0;
        }

#pragma unroll 4
        for (int m = 0; m < MM; ++m) {
            float4 gb = g[m];
            float a = ga[m];
#pragma unroll
            for (int j = 0; j < 4; ++j) {
                float lx = fmaxf(gb.x, p[j].x), ly = fmaxf(gb.y, p[j].y);
                float rx = fminf(gb.z, p[j].z), ry = fminf(gb.w, p[j].w);
                float w = fmaxf(rx - lx, 0.0f), h = fmaxf(ry - ly, 0.0f);
                float inter = __fmul_rn(w, h);
                float uni = __fsub_rn(__fadd_rn(a, ap[j]), inter);
                if (__fmul_rn(inter, bU[j]) > __fmul_rn(bI[j], uni)) {
                    bI[j] = inter; bU[j] = uni; bx[j] = m;
                }
            }
        }

#pragma unroll
        for (int j = 0; j < 4; ++j) {
            float v = __fdiv_rn(bI[j], bU[j]);
            mv[n[j]] = v;
            mi[n[j]] = (float)bx[j];
            bool fg = (v >= 0.5f);
            unsigned u = f2s(pr[j]);
            unsigned bn = (unsigned)(pr[j] * 256.0f); if (bn > 255u) bn = 255u;
            g_keyFg[n[j]] = fg ? u : 0u;
            g_keyBg[n[j]] = fg ? 0u : u;
            atomicAdd(&g_hist[(fg ? 0 : 1) * BB * NBINS + (b) * NBINS + bn], 1u);
        }
    }

    // ===================== Phase 2: grid barrier ============================
    // All 128 CTAs are resident (128 < 148 SMs) => spin is deadlock-free.
    __syncthreads();
    if (tid == 0) {
        __threadfence();
        unsigned old = atomicAdd(&g_arrive, 1u);
        unsigned target = ((old >> 7) + 1u) << 7;   // this launch's 128 arrivals
        while (atomicAdd(&g_arrive, 0u) < target) {}
        __threadfence();
    }
    __syncthreads();

    // ===================== Phase 3: sample (CTAs 0..31) =====================
    if (c >= 32) return;

    const int  b      = c & 15;
    const bool wantFg = (c < 16);
    const int  K      = wantFg ? NFG : NBG;
    const int  off    = wantFg ? 0   : NFG;

    const unsigned* keys = (wantFg ? g_keyFg : g_keyBg) + b * NN;
    unsigned* histSlice = &g_hist[(wantFg ? 0 : 1) * BB * NBINS + b * NBINS];

    // 32 contiguous keys per thread (L2-warm)
    unsigned u[32];
    {
        const uint4* k4 = (const uint4*)(keys + tid * 32);
#pragma unroll
        for (int e = 0; e < 8; ++e) {
            uint4 a = k4[e];
            u[e * 4 + 0] = a.x; u[e * 4 + 1] = a.y;
            u[e * 4 + 2] = a.z; u[e * 4 + 3] = a.w;
        }
    }

    if (tid == 0) listCnt = 0;

    // Warp 0: suffix-scan histogram -> threshold bin T, total count
    if (wid == 0) {
        unsigned h[8];
#pragma unroll
        for (int e = 0; e < 8; ++e) h[e] = histSlice[lane * 8 + e];
        unsigned lsum = 0;
#pragma unroll
        for (int e = 0; e < 8; ++e) lsum += h[e];
        unsigned s = lsum;
#pragma unroll
        for (int d = 1; d < 32; d <<= 1) {
            unsigned v = __shfl_down_sync(0xffffffffu, s, d);
            if (lane + d < 32) s += v;
        }
        unsigned total = __shfl_sync(0xffffffffu, s, 0);
        unsigned run = s - lsum;                 // suffix over lanes > lane
        int myT = 0;
#pragma unroll
        for (int e = 7; e >= 0; --e) {
            unsigned sufE = run + h[e];
            if ((int)sufE >= K && (int)run < K) myT = lane * 8 + e;
            run = sufE;
        }
#pragma unroll
        for (int d = 1; d < 32; d <<= 1) {
            int v = __shfl_xor_sync(0xffffffffu, myT, d);
            if (v > myT) myT = v;
        }
        if (lane == 0) { sh_T = myT; sh_total = (int)total; }
    }
    __syncthreads();

    const int T = sh_T;
    const int total = sh_total;

    // Compact candidates (bin >= T): one atomic per warp (two-pass ballots)
    {
        unsigned mymask = 0;
        unsigned cnt = 0;
#pragma unroll
        for (int e = 0; e < 32; ++e) {
            bool tk = false;
            if (u[e] != 0u) {
                float p = __uint_as_float(u[e] ^ 0x80000000u);
                unsigned bn = (unsigned)(p * 256.0f); if (bn > 255u) bn = 255u;
                tk = ((int)bn >= T);
            }
            unsigned ball = __ballot_sync(0xffffffffu, tk);
            if (tk) mymask |= 1u << e;
            cnt += __popc(ball);
        }
        int base = 0;
        if (lane == 0 && cnt) base = atomicAdd(&listCnt, (int)cnt);
        base = __shfl_sync(0xffffffffu, base, 0);
        unsigned pre = 0;
        const unsigned lmask = (lane == 0) ? 0u : (0xffffffffu >> (32 - lane));
#pragma unroll
        for (int e = 0; e < 32; ++e) {
            unsigned ball = __ballot_sync(0xffffffffu, (mymask >> e) & 1u);
            if ((mymask >> e) & 1u) {
                int pos = base + (int)pre + __popc(ball & lmask);
                if (pos < LISTCAP) {
                    int t = tid * 32 + e;
                    list[pos] = ((unsigned long long)u[e] << 32) |
                                (unsigned long long)(0xFFFFFFFFu - (unsigned)t);
                }
            }
            pre += __popc(ball);
        }
    }
    __syncthreads();

    // Exact ranking: thread handles candidates tid and tid+256
    {
        int S = listCnt < LISTCAP ? listCnt : LISTCAP;
        unsigned long long k0 = 0, k1 = 0;
        if (tid < S) k0 = list[tid];
        if (tid + 256 < S) k1 = list[tid + 256];
        int r0 = 0, r1 = 0;
        for (int j = 0; j < S; ++j) {
            unsigned long long v = list[j];
            r0 += (v > k0);
            r1 += (v > k1);
        }
        if (tid < S && r0 < K) {
            int idx = (int)(0xFFFFFFFFu - (unsigned)(k0 & 0xFFFFFFFFull));
            int midx = (int)mi[b * NN + idx];
            s_idx[b * SAMP + off + r0] = (float)idx;
            s_gt [b * SAMP + off + r0] = (float)midx;
            s_cls[b * SAMP + off + r0] = wantFg ? (float)gtc[b * MM + midx] : 80.0f;
        }
        if (tid + 256 < S && r1 < K) {
            int idx = (int)(0xFFFFFFFFu - (unsigned)(k1 & 0xFFFFFFFFull));
            int midx = (int)mi[b * NN + idx];
            s_idx[b * SAMP + off + r1] = (float)idx;
            s_gt [b * SAMP + off + r1] = (float)midx;
            s_cls[b * SAMP + off + r1] = wantFg ? (float)gtc[b * MM + midx] : 80.0f;
        }
    }

    // Fill tail (total < K) with not-selected indices, ascending
    if (total < K) {
        const int need = K - total;
        unsigned msk = 0;
        int cc = 0;
#pragma unroll
        for (int e = 0; e < 32; ++e)
            if (u[e] == 0u) { msk |= 1u << e; ++cc; }
        int inc = cc;
#pragma unroll
        for (int d = 1; d < 32; d <<= 1) {
            int v = __shfl_up_sync(0xffffffffu, inc, d);
            if (lane >= d) inc += v;
        }
        if (lane == 31) warpsum[wid] = (unsigned)inc;
        __syncthreads();
        if (wid == 0 && lane < 8) {
            int wv = (int)warpsum[lane];
            int winc = wv;
#pragma unroll
            for (int d = 1; d < 8; d <<= 1) {
                int v = __shfl_up_sync(0xffu, winc, d);
                if (lane >= d) winc += v;
            }
            warpsum[lane] = (unsigned)(winc - wv);
        }
        __syncthreads();
        int p = (int)warpsum[wid] + (inc - cc);
        const int base_e = tid * 32;
#pragma unroll
        for (int e = 0; e < 32; ++e) {
            if (msk & (1u << e)) {
                if (p < need) {
                    int slot = b * SAMP + off + total + p;
                    s_idx[slot] = (float)(base_e + e);
                    s_cls[slot] = -1.0f;
                    s_gt [slot] = -1.0f;
                }
                ++p;
            }
        }
    }
    __syncthreads();

    // Zero this block's histogram slice for the next graph replay
    if (tid < NBINS) histSlice[tid] = 0u;
}

extern "C" void kernel_launch(void* const* d_in, const int* in_sizes, int n_in,
                              void* d_out, int out_size) {
    const float* gt_boxes   = (const float*)d_in[0];   // [B,M,4]
    const int*   gt_classes = (const int*)  d_in[1];   // [B,M]
    const float* prop_boxes = (const float*)d_in[2];   // [B,N,4]
    const float* rand_pri   = (const float*)d_in[3];   // [B,N]

    float* out = (float*)d_out;
    float* matched_vals = out;                        // B*N
    float* matched_idxs = out + BB * NN;              // B*N
    float* sampled_idxs = out + 2 * BB * NN;          // B*512
    float* sampled_cls  = sampled_idxs + BB * SAMP;   // B*512
    float* sampled_gt   = sampled_cls  + BB * SAMP;   // B*512

    fused_kernel<<<NCTA, NTHR>>>((const float4*)gt_boxes,
                                 (const float4*)prop_boxes,
                                 rand_pri, gt_classes,
                                 matched_vals, matched_idxs,
                                 sampled_idxs, sampled_cls, sampled_gt);
}

// round 10
// speedup vs baseline: 1.1851x; 1.1851x over previous
#include <cuda_runtime.h>
#include <cuda_bf16.h>

#define BB    16
#define MM    256
#define NN    8192
#define NFG   128
#define NBG   384
#define SAMP  512
#define NBINS 256
#define LISTCAP 2048
#define NCTA  256
#define NTHR  256

__device__ unsigned g_keyFg[BB * NN];          // f2s(pri) if fg else 0
__device__ unsigned g_keyBg[BB * NN];          // f2s(pri) if bg else 0
__device__ unsigned g_hist[2 * BB * NBINS];    // [side][b][bin]; zeroed in phase3
__device__ unsigned g_arrive;                  // monotone grid-barrier counter

static __device__ __forceinline__ unsigned f2s(float f) {
    unsigned u = __float_as_uint(f);
    return (u & 0x80000000u) ? ~u : (u | 0x80000000u);
}

__global__ __launch_bounds__(NTHR, 2)
void fused_kernel(const float4* __restrict__ gt,
                  const float4* __restrict__ prop,
                  const float*  __restrict__ pri,
                  const int*    __restrict__ gtc,
                  float* __restrict__ mv,
                  float* __restrict__ mi,
                  float* __restrict__ s_idx,
                  float* __restrict__ s_cls,
                  float* __restrict__ s_gt) {
    __shared__ float4 g[MM];
    __shared__ float  ga[MM];
    __shared__ unsigned long long list[LISTCAP];
    __shared__ unsigned warpsum[8];
    __shared__ int listCnt, sh_T, sh_total;

    const int tid = threadIdx.x;                 // 256
    const int c   = blockIdx.x;                  // 256
    const int lane = tid & 31;
    const int wid  = tid >> 5;

    // ============ Phase 1: match (16 CTAs per batch, 2 props/thread) ========
    {
        const int b = c >> 4;                    // batch
        const int q = c & 15;                    // 512-proposal slice
        {
            float4 v = gt[b * MM + tid];
            g[tid] = v;
            ga[tid] = __fmul_rn(v.z - v.x, v.w - v.y);
        }
        __syncthreads();

        const int n0 = b * NN + q * 512 + tid;
        const int n1 = n0 + 256;
        float4 p0 = prop[n0];
        float4 p1 = prop[n1];
        float pr0 = pri[n0];
        float pr1 = pri[n1];
        float ap0 = __fmul_rn(p0.z - p0.x, p0.w - p0.y);
        float ap1 = __fmul_rn(p1.z - p1.x, p1.w - p1.y);

        float bI0 = -1.0f, bU0 = 1.0f, bI1 = -1.0f, bU1 = 1.0f;
        int bx0 = 0, bx1 = 0;

#pragma unroll 8
        for (int m = 0; m < MM; ++m) {
            float4 gb = g[m];
            float a = ga[m];
            {
                float lx = fmaxf(gb.x, p0.x), ly = fmaxf(gb.y, p0.y);
                float rx = fminf(gb.z, p0.z), ry = fminf(gb.w, p0.w);
                float w = fmaxf(rx - lx, 0.0f), h = fmaxf(ry - ly, 0.0f);
                float inter = __fmul_rn(w, h);
                float uni = __fsub_rn(__fadd_rn(a, ap0), inter);
                if (__fmul_rn(inter, bU0) > __fmul_rn(bI0, uni)) {
                    bI0 = inter; bU0 = uni; bx0 = m;
                }
            }
            {
                float lx = fmaxf(gb.x, p1.x), ly = fmaxf(gb.y, p1.y);
                float rx = fminf(gb.z, p1.z), ry = fminf(gb.w, p1.w);
                float w = fmaxf(rx - lx, 0.0f), h = fmaxf(ry - ly, 0.0f);
                float inter = __fmul_rn(w, h);
                float uni = __fsub_rn(__fadd_rn(a, ap1), inter);
                if (__fmul_rn(inter, bU1) > __fmul_rn(bI1, uni)) {
                    bI1 = inter; bU1 = uni; bx1 = m;
                }
            }
        }

        {
            float v0 = __fdiv_rn(bI0, bU0);
            float v1 = __fdiv_rn(bI1, bU1);
            mv[n0] = v0;  mi[n0] = (float)bx0;
            mv[n1] = v1;  mi[n1] = (float)bx1;
            bool fg0 = (v0 >= 0.5f);
            bool fg1 = (v1 >= 0.5f);
            unsigned u0 = f2s(pr0), u1 = f2s(pr1);
            unsigned bn0 = (unsigned)(pr0 * 256.0f); if (bn0 > 255u) bn0 = 255u;
            unsigned bn1 = (unsigned)(pr1 * 256.0f); if (bn1 > 255u) bn1 = 255u;
            g_keyFg[n0] = fg0 ? u0 : 0u;
            g_keyBg[n0] = fg0 ? 0u : u0;
            g_keyFg[n1] = fg1 ? u1 : 0u;
            g_keyBg[n1] = fg1 ? 0u : u1;
            atomicAdd(&g_hist[(fg0 ? 0 : 1) * BB * NBINS + b * NBINS + bn0], 1u);
            atomicAdd(&g_hist[(fg1 ? 0 : 1) * BB * NBINS + b * NBINS + bn1], 1u);
        }
    }

    // ===================== Phase 2: grid barrier ============================
    // 256 CTAs, 2 resident per SM (launch_bounds) on 148 SMs => all resident.
    __syncthreads();
    if (tid == 0) {
        __threadfence();
        unsigned old = atomicAdd(&g_arrive, 1u);
        unsigned target = ((old >> 8) + 1u) << 8;   // this launch's 256 arrivals
        while (atomicAdd(&g_arrive, 0u) < target) {}
        __threadfence();
    }
    __syncthreads();

    // ===================== Phase 3: sample (CTAs 0..31) =====================
    if (c >= 32) return;

    const int  b      = c & 15;
    const bool wantFg = (c < 16);
    const int  K      = wantFg ? NFG : NBG;
    const int  off    = wantFg ? 0   : NFG;

    const unsigned* keys = (wantFg ? g_keyFg : g_keyBg) + b * NN;
    unsigned* histSlice = &g_hist[(wantFg ? 0 : 1) * BB * NBINS + b * NBINS];

    // 32 contiguous keys per thread (L2-warm)
    unsigned u[32];
    {
        const uint4* k4 = (const uint4*)(keys + tid * 32);
#pragma unroll
        for (int e = 0; e < 8; ++e) {
            uint4 a = k4[e];
            u[e * 4 + 0] = a.x; u[e * 4 + 1] = a.y;
            u[e * 4 + 2] = a.z; u[e * 4 + 3] = a.w;
        }
    }

    if (tid == 0) listCnt = 0;

    // Warp 0: suffix-scan histogram -> threshold bin T, total count
    if (wid == 0) {
        unsigned h[8];
#pragma unroll
        for (int e = 0; e < 8; ++e) h[e] = histSlice[lane * 8 + e];
        unsigned lsum = 0;
#pragma unroll
        for (int e = 0; e < 8; ++e) lsum += h[e];
        unsigned s = lsum;
#pragma unroll
        for (int d = 1; d < 32; d <<= 1) {
            unsigned v = __shfl_down_sync(0xffffffffu, s, d);
            if (lane + d < 32) s += v;
        }
        unsigned total = __shfl_sync(0xffffffffu, s, 0);
        unsigned run = s - lsum;                 // suffix over lanes > lane
        int myT = 0;
#pragma unroll
        for (int e = 7; e >= 0; --e) {
            unsigned sufE = run + h[e];
            if ((int)sufE >= K && (int)run < K) myT = lane * 8 + e;
            run = sufE;
        }
#pragma unroll
        for (int d = 1; d < 32; d <<= 1) {
            int v = __shfl_xor_sync(0xffffffffu, myT, d);
            if (v > myT) myT = v;
        }
        if (lane == 0) { sh_T = myT; sh_total = (int)total; }
    }
    __syncthreads();

    const int T = sh_T;
    const int total = sh_total;

    // Compact candidates (bin >= T): one atomic per warp
    {
        unsigned mymask = 0;
        unsigned cnt = 0;
#pragma unroll
        for (int e = 0; e < 32; ++e) {
            bool tk = false;
            if (u[e] != 0u) {
                float p = __uint_as_float(u[e] ^ 0x80000000u);
                unsigned bn = (unsigned)(p * 256.0f); if (bn > 255u) bn = 255u;
                tk = ((int)bn >= T);
            }
            unsigned ball = __ballot_sync(0xffffffffu, tk);
            if (tk) mymask |= 1u << e;
            cnt += __popc(ball);
        }
        int base = 0;
        if (lane == 0 && cnt) base = atomicAdd(&listCnt, (int)cnt);
        base = __shfl_sync(0xffffffffu, base, 0);
        unsigned pre = 0;
        const unsigned lmask = (lane == 0) ? 0u : (0xffffffffu >> (32 - lane));
#pragma unroll
        for (int e = 0; e < 32; ++e) {
            unsigned ball = __ballot_sync(0xffffffffu, (mymask >> e) & 1u);
            if ((mymask >> e) & 1u) {
                int pos = base + (int)pre + __popc(ball & lmask);
                if (pos < LISTCAP) {
                    int t = tid * 32 + e;
                    list[pos] = ((unsigned long long)u[e] << 32) |
                                (unsigned long long)(0xFFFFFFFFu - (unsigned)t);
                }
            }
            pre += __popc(ball);
        }
    }
    __syncthreads();

    // Exact ranking over ALL candidates (strided; covers any S <= LISTCAP)
    {
        int S = listCnt < LISTCAP ? listCnt : LISTCAP;
        for (int i = tid; i < S; i += NTHR) {
            unsigned long long ki = list[i];
            int rank = 0;
            for (int j = 0; j < S; ++j) rank += (list[j] > ki);
            if (rank < K) {
                int idx = (int)(0xFFFFFFFFu - (unsigned)(ki & 0xFFFFFFFFull));
                int midx = (int)mi[b * NN + idx];
                s_idx[b * SAMP + off + rank] = (float)idx;
                s_gt [b * SAMP + off + rank] = (float)midx;
                s_cls[b * SAMP + off + rank] = wantFg ? (float)gtc[b * MM + midx] : 80.0f;
            }
        }
    }

    // Fill tail (total < K) with not-selected indices, ascending
    if (total < K) {
        const int need = K - total;
        unsigned msk = 0;
        int cc = 0;
#pragma unroll
        for (int e = 0; e < 32; ++e)
            if (u[e] == 0u) { msk |= 1u << e; ++cc; }
        int inc = cc;
#pragma unroll
        for (int d = 1; d < 32; d <<= 1) {
            int v = __shfl_up_sync(0xffffffffu, inc, d);
            if (lane >= d) inc += v;
        }
        if (lane == 31) warpsum[wid] = (unsigned)inc;
        __syncthreads();
        if (wid == 0 && lane < 8) {
            int wv = (int)warpsum[lane];
            int winc = wv;
#pragma unroll
            for (int d = 1; d < 8; d <<= 1) {
                int v = __shfl_up_sync(0xffu, winc, d);
                if (lane >= d) winc += v;
            }
            warpsum[lane] = (unsigned)(winc - wv);
        }
        __syncthreads();
        int p = (int)warpsum[wid] + (inc - cc);
        const int base_e = tid * 32;
#pragma unroll
        for (int e = 0; e < 32; ++e) {
            if (msk & (1u << e)) {
                if (p < need) {
                    int slot = b * SAMP + off + total + p;
                    s_idx[slot] = (float)(base_e + e);
                    s_cls[slot] = -1.0f;
                    s_gt [slot] = -1.0f;
                }
                ++p;
            }
        }
    }
    __syncthreads();

    // Zero this block's histogram slice for the next graph replay
    if (tid < NBINS) histSlice[tid] = 0u;
}

extern "C" void kernel_launch(void* const* d_in, const int* in_sizes, int n_in,
                              void* d_out, int out_size) {
    const float* gt_boxes   = (const float*)d_in[0];   // [B,M,4]
    const int*   gt_classes = (const int*)  d_in[1];   // [B,M]
    const float* prop_boxes = (const float*)d_in[2];   // [B,N,4]
    const float* rand_pri   = (const float*)d_in[3];   // [B,N]

    float* out = (float*)d_out;
    float* matched_vals = out;                        // B*N
    float* matched_idxs = out + BB * NN;              // B*N
    float* sampled_idxs = out + 2 * BB * NN;          // B*512
    float* sampled_cls  = sampled_idxs + BB * SAMP;   // B*512
    float* sampled_gt   = sampled_cls  + BB * SAMP;   // B*512

    fused_kernel<<<NCTA, NTHR>>>((const float4*)gt_boxes,
                                 (const float4*)prop_boxes,
                                 rand_pri, gt_classes,
                                 matched_vals, matched_idxs,
                                 sampled_idxs, sampled_cls, sampled_gt);
}

// round 11
// speedup vs baseline: 1.1921x; 1.0059x over previous
#include <cuda_runtime.h>
#include <cuda_bf16.h>

#define BB    16
#define MM    256
#define NN    8192
#define NFG   128
#define NBG   384
#define SAMP  512
#define NBINS 256
#define LISTCAP 2048
#define NCTA  512
#define NTHR  256

__device__ unsigned g_keyFg[BB * NN];          // f2s(pri) if fg else 0
__device__ unsigned g_keyBg[BB * NN];          // f2s(pri) if bg else 0
__device__ unsigned g_hist[2 * BB * NBINS];    // [side][b][bin]; zeroed in phase3
__device__ unsigned g_arrive;                  // monotone grid-barrier counter

static __device__ __forceinline__ unsigned f2s(float f) {
    unsigned u = __float_as_uint(f);
    return (u & 0x80000000u) ? ~u : (u | 0x80000000u);
}

__global__ __launch_bounds__(NTHR, 4)
void fused_kernel(const float4* __restrict__ gt,
                  const float4* __restrict__ prop,
                  const float*  __restrict__ pri,
                  const int*    __restrict__ gtc,
                  float* __restrict__ mv,
                  float* __restrict__ mi,
                  float* __restrict__ s_idx,
                  float* __restrict__ s_cls,
                  float* __restrict__ s_gt) {
    __shared__ float4 g[MM];
    __shared__ float  ga[MM];
    __shared__ unsigned long long list[LISTCAP];
    __shared__ unsigned warpsum[8];
    __shared__ int listCnt, sh_T, sh_total;

    const int tid = threadIdx.x;                 // 256
    const int c   = blockIdx.x;                  // 512
    const int lane = tid & 31;
    const int wid  = tid >> 5;

    // ======== Phase 1: match (32 CTAs per batch, 1 proposal/thread) =========
    {
        const int b = c >> 5;                    // batch
        const int q = c & 31;                    // 256-proposal slice
        {
            float4 v = gt[b * MM + tid];
            g[tid] = v;
            ga[tid] = __fmul_rn(v.z - v.x, v.w - v.y);
        }
        __syncthreads();

        const int n0 = b * NN + q * 256 + tid;
        float4 p0 = prop[n0];
        float pr0 = pri[n0];
        float ap0 = __fmul_rn(p0.z - p0.x, p0.w - p0.y);

        float bI0 = -1.0f, bU0 = 1.0f;
        int bx0 = 0;

#pragma unroll 4
        for (int m = 0; m < MM; ++m) {
            float4 gb = g[m];
            float a = ga[m];
            float lx = fmaxf(gb.x, p0.x), ly = fmaxf(gb.y, p0.y);
            float rx = fminf(gb.z, p0.z), ry = fminf(gb.w, p0.w);
            float w = fmaxf(rx - lx, 0.0f), h = fmaxf(ry - ly, 0.0f);
            float inter = __fmul_rn(w, h);
            float uni = __fsub_rn(__fadd_rn(a, ap0), inter);
            if (__fmul_rn(inter, bU0) > __fmul_rn(bI0, uni)) {
                bI0 = inter; bU0 = uni; bx0 = m;
            }
        }

        float v0 = __fdiv_rn(bI0, bU0);
        mv[n0] = v0;
        mi[n0] = (float)bx0;
        bool fg0 = (v0 >= 0.5f);
        unsigned u0 = f2s(pr0);
        unsigned bn0 = (unsigned)(pr0 * 256.0f); if (bn0 > 255u) bn0 = 255u;
        g_keyFg[n0] = fg0 ? u0 : 0u;
        g_keyBg[n0] = fg0 ? 0u : u0;
        atomicAdd(&g_hist[(fg0 ? 0 : 1) * BB * NBINS + b * NBINS + bn0], 1u);
    }

    // ===================== Phase 2: grid barrier ============================
    // 512 CTAs, 4 resident/SM (<=64 regs) on 148 SMs: 592 slots => all resident.
    __syncthreads();
    if (tid == 0) {
        __threadfence();
        unsigned old = atomicAdd(&g_arrive, 1u);
        unsigned target = ((old >> 9) + 1u) << 9;   // this launch's 512 arrivals
        while (atomicAdd(&g_arrive, 0u) < target) {}
        __threadfence();
    }
    __syncthreads();

    // ===================== Phase 3: sample (CTAs 0..31) =====================
    if (c >= 32) return;

    const int  b      = c & 15;
    const bool wantFg = (c < 16);
    const int  K      = wantFg ? NFG : NBG;
    const int  off    = wantFg ? 0   : NFG;

    const unsigned* keys = (wantFg ? g_keyFg : g_keyBg) + b * NN;
    unsigned* histSlice = &g_hist[(wantFg ? 0 : 1) * BB * NBINS + b * NBINS];

    if (tid == 0) listCnt = 0;

    // Warp 0: suffix-scan histogram -> threshold bin T, total count
    if (wid == 0) {
        unsigned h[8];
#pragma unroll
        for (int e = 0; e < 8; ++e) h[e] = histSlice[lane * 8 + e];
        unsigned lsum = 0;
#pragma unroll
        for (int e = 0; e < 8; ++e) lsum += h[e];
        unsigned s = lsum;
#pragma unroll
        for (int d = 1; d < 32; d <<= 1) {
            unsigned v = __shfl_down_sync(0xffffffffu, s, d);
            if (lane + d < 32) s += v;
        }
        unsigned total = __shfl_sync(0xffffffffu, s, 0);
        unsigned run = s - lsum;                 // suffix over lanes > lane
        int myT = 0;
#pragma unroll
        for (int e = 7; e >= 0; --e) {
            unsigned sufE = run + h[e];
            if ((int)sufE >= K && (int)run < K) myT = lane * 8 + e;
            run = sufE;
        }
#pragma unroll
        for (int d = 1; d < 32; d <<= 1) {
            int v = __shfl_xor_sync(0xffffffffu, myT, d);
            if (v > myT) myT = v;
        }
        if (lane == 0) { sh_T = myT; sh_total = (int)total; }
    }
    __syncthreads();

    const int T = sh_T;
    const int total = sh_total;
    const uint4* k4 = (const uint4*)(keys + tid * 32);

    // Pass A: stream keys; build take-mask (1 bit/key) + zero-mask; counts
    unsigned takemask = 0, zeromask = 0;
    {
#pragma unroll
        for (int e8 = 0; e8 < 8; ++e8) {
            uint4 a = k4[e8];
            unsigned uu[4] = {a.x, a.y, a.z, a.w};
#pragma unroll
            for (int v = 0; v < 4; ++v) {
                int e = e8 * 4 + v;
                unsigned ue = uu[v];
                if (ue == 0u) zeromask |= 1u << e;
                else {
                    float p = __uint_as_float(ue ^ 0x80000000u);
                    unsigned bn = (unsigned)(p * 256.0f); if (bn > 255u) bn = 255u;
                    if ((int)bn >= T) takemask |= 1u << e;
                }
            }
        }
    }

    // Compaction: one atomic per warp, then re-stream keys for values
    {
        unsigned cnt = 0;
        unsigned ballv[32];
#pragma unroll
        for (int e = 0; e < 32; ++e) {
            ballv[e] = __ballot_sync(0xffffffffu, (takemask >> e) & 1u);
            cnt += __popc(ballv[e]);
        }
        int base = 0;
        if (lane == 0 && cnt) base = atomicAdd(&listCnt, (int)cnt);
        base = __shfl_sync(0xffffffffu, base, 0);
        unsigned pre = 0;
        const unsigned lmask = (lane == 0) ? 0u : (0xffffffffu >> (32 - lane));
#pragma unroll
        for (int e8 = 0; e8 < 8; ++e8) {
            uint4 a = k4[e8];
            unsigned uu[4] = {a.x, a.y, a.z, a.w};
#pragma unroll
            for (int v = 0; v < 4; ++v) {
                int e = e8 * 4 + v;
                if ((takemask >> e) & 1u) {
                    int pos = base + (int)pre + __popc(ballv[e] & lmask);
                    if (pos < LISTCAP) {
                        int t = tid * 32 + e;
                        list[pos] = ((unsigned long long)uu[v] << 32) |
                                    (unsigned long long)(0xFFFFFFFFu - (unsigned)t);
                    }
                }
                pre += __popc(ballv[e]);
            }
        }
    }
    __syncthreads();

    // Exact ranking over ALL candidates
    {
        int S = listCnt < LISTCAP ? listCnt : LISTCAP;
        for (int i = tid; i < S; i += NTHR) {
            unsigned long long ki = list[i];
            int rank = 0;
            for (int j = 0; j < S; ++j) rank += (list[j] > ki);
            if (rank < K) {
                int idx = (int)(0xFFFFFFFFu - (unsigned)(ki & 0xFFFFFFFFull));
                int midx = (int)mi[b * NN + idx];
                s_idx[b * SAMP + off + rank] = (float)idx;
                s_gt [b * SAMP + off + rank] = (float)midx;
                s_cls[b * SAMP + off + rank] = wantFg ? (float)gtc[b * MM + midx] : 80.0f;
            }
        }
    }

    // Fill tail (total < K) with not-selected indices, ascending
    if (total < K) {
        const int need = K - total;
        int cc = __popc(zeromask);
        int inc = cc;
#pragma unroll
        for (int d = 1; d < 32; d <<= 1) {
            int v = __shfl_up_sync(0xffffffffu, inc, d);
            if (lane >= d) inc += v;
        }
        if (lane == 31) warpsum[wid] = (unsigned)inc;
        __syncthreads();
        if (wid == 0 && lane < 8) {
            int wv = (int)warpsum[lane];
            int winc = wv;
#pragma unroll
            for (int d = 1; d < 8; d <<= 1) {
                int v = __shfl_up_sync(0xffu, winc, d);
                if (lane >= d) winc += v;
            }
            warpsum[lane] = (unsigned)(winc - wv);
        }
        __syncthreads();
        int p = (int)warpsum[wid] + (inc - cc);
        const int base_e = tid * 32;
#pragma unroll
        for (int e = 0; e < 32; ++e) {
            if (zeromask & (1u << e)) {
                if (p < need) {
                    int slot = b * SAMP + off + total + p;
                    s_idx[slot] = (float)(base_e + e);
                    s_cls[slot] = -1.0f;
                    s_gt [slot] = -1.0f;
                }
                ++p;
            }
        }
    }
    __syncthreads();

    // Zero this block's histogram slice for the next graph replay
    if (tid < NBINS) histSlice[tid] = 0u;
}

extern "C" void kernel_launch(void* const* d_in, const int* in_sizes, int n_in,
                              void* d_out, int out_size) {
    const float* gt_boxes   = (const float*)d_in[0];   // [B,M,4]
    const int*   gt_classes = (const int*)  d_in[1];   // [B,M]
    const float* prop_boxes = (const float*)d_in[2];   // [B,N,4]
    const float* rand_pri   = (const float*)d_in[3];   // [B,N]

    float* out = (float*)d_out;
    float* matched_vals = out;                        // B*N
    float* matched_idxs = out + BB * NN;              // B*N
    float* sampled_idxs = out + 2 * BB * NN;          // B*512
    float* sampled_cls  = sampled_idxs + BB * SAMP;   // B*512
    float* sampled_gt   = sampled_cls  + BB * SAMP;   // B*512

    fused_kernel<<<NCTA, NTHR>>>((const float4*)gt_boxes,
                                 (const float4*)prop_boxes,
                                 rand_pri, gt_classes,
                                 matched_vals, matched_idxs,
                                 sampled_idxs, sampled_cls, sampled_gt);
}